// round 14
// baseline (speedup 1.0000x reference)
#include <cuda_runtime.h>
#include <cuda_fp16.h>
#include <math.h>
#include <stdint.h>

// -------------------- problem constants --------------------
#define T      4096
#define HDIM   2048
#define FFN    1024
#define NEXP   8
#define TOPK   2
#define SLOTS  (T * TOPK)

// -------------------- scratch (device globals; no allocs) --------------------
__device__ int   g_topk_idx[T * TOPK];
__device__ float g_topk_w[T * TOPK];
__device__ int   g_cnt[NEXP];
__device__ int   g_cur[NEXP];
__device__ int   g_off[NEXP + 1];
__device__ int   g_perm[SLOTS];
__device__ float g_permw[SLOTS];

__device__ __half g_x [(size_t)T * HDIM];
__device__ __half g_w1[(size_t)NEXP * FFN * HDIM];
__device__ __half g_w3[(size_t)NEXP * FFN * HDIM];
__device__ __half g_w2[(size_t)NEXP * HDIM * FFN];
__device__ __half g_G [(size_t)SLOTS * FFN];

// -------------------- helpers --------------------
__device__ __forceinline__ uint32_t smem_u32(const void* p) {
    uint32_t a;
    asm("{ .reg .u64 t; cvta.to.shared.u64 t, %1; cvt.u32.u64 %0, t; }" : "=r"(a) : "l"(p));
    return a;
}
__device__ __forceinline__ void cpa16(uint32_t dst, const void* src, bool v) {
    uint64_t g = __cvta_generic_to_global(src);
    int sz = v ? 16 : 0;
    asm volatile("cp.async.cg.shared.global [%0], [%1], 16, %2;"
                 :: "r"(dst), "l"(g), "r"(sz) : "memory");
}
#define CP_COMMIT() asm volatile("cp.async.commit_group;" ::: "memory")
#define CP_WAIT2()  asm volatile("cp.async.wait_group 2;" ::: "memory")

#define LDM4(r, a) \
    asm volatile("ldmatrix.sync.aligned.m8n8.x4.shared.b16 {%0,%1,%2,%3}, [%4];" \
        : "=r"((r)[0]), "=r"((r)[1]), "=r"((r)[2]), "=r"((r)[3]) : "r"(a))

#define MMAH(d, a, b0, b1) \
    asm volatile("mma.sync.aligned.m16n8k16.row.col.f32.f16.f16.f32 " \
        "{%0,%1,%2,%3},{%4,%5,%6,%7},{%8,%9},{%0,%1,%2,%3};" \
        : "+f"((d)[0]), "+f"((d)[1]), "+f"((d)[2]), "+f"((d)[3]) \
        : "r"((a)[0]), "r"((a)[1]), "r"((a)[2]), "r"((a)[3]), "r"(b0), "r"(b1))

// smem row stride: 32 fp16 (64B) + 16B pad = 80 B (conflict-free ldmatrix)
#define SROW 80

// -------------------- fused prep: router + zero_out + convert ---------------
#define RBLK (T / 16)                                    // 256 (2 tokens/warp)
#define ZBLK (T * (HDIM / 4) / 256)                      // 8192
#define CBLK ((3u * (NEXP * FFN * HDIM / 8) + 255) / 256)   // 24576
#define PREP_BLOCKS (RBLK + ZBLK + CBLK)

__global__ void prep_kernel(const float* __restrict__ x,
                            const float* __restrict__ Wg,
                            const float* __restrict__ bias,
                            const float* __restrict__ W1,
                            const float* __restrict__ W3,
                            const float* __restrict__ W2,
                            float* __restrict__ out) {
    int b = blockIdx.x;

    if (b < RBLK) {
        int warp = (b * 256 + threadIdx.x) >> 5;
        int lane = threadIdx.x & 31;
        if (b == 0 && threadIdx.x < NEXP) {
            g_cnt[threadIdx.x] = 0;
            g_cur[threadIdx.x] = 0;
        }
        int t0 = warp * 2, t1 = t0 + 1;
        const float* xr0 = x + (size_t)t0 * HDIM;
        const float* xr1 = x + (size_t)t1 * HDIM;
        __half* xo0 = g_x + (size_t)t0 * HDIM;
        __half* xo1 = g_x + (size_t)t1 * HDIM;

        float a0[NEXP], a1[NEXP];
#pragma unroll
        for (int e = 0; e < NEXP; e++) { a0[e] = 0.f; a1[e] = 0.f; }

        for (int k = lane * 4; k < HDIM; k += 32 * 4) {
            float4 xv0 = *(const float4*)(xr0 + k);
            float4 xv1 = *(const float4*)(xr1 + k);
            union { uint2 u; __half2 h[2]; } c0, c1;
            c0.h[0] = __halves2half2(__float2half(xv0.x), __float2half(xv0.y));
            c0.h[1] = __halves2half2(__float2half(xv0.z), __float2half(xv0.w));
            c1.h[0] = __halves2half2(__float2half(xv1.x), __float2half(xv1.y));
            c1.h[1] = __halves2half2(__float2half(xv1.z), __float2half(xv1.w));
            *(uint2*)(xo0 + k) = c0.u;
            *(uint2*)(xo1 + k) = c1.u;
#pragma unroll
            for (int e = 0; e < NEXP; e++) {
                float4 wv = *(const float4*)(Wg + (size_t)e * HDIM + k);
                a0[e] += xv0.x * wv.x + xv0.y * wv.y + xv0.z * wv.z + xv0.w * wv.w;
                a1[e] += xv1.x * wv.x + xv1.y * wv.y + xv1.z * wv.z + xv1.w * wv.w;
            }
        }
#pragma unroll
        for (int e = 0; e < NEXP; e++) {
#pragma unroll
            for (int o = 16; o > 0; o >>= 1) {
                a0[e] += __shfl_xor_sync(0xFFFFFFFFu, a0[e], o);
                a1[e] += __shfl_xor_sync(0xFFFFFFFFu, a1[e], o);
            }
        }
        if (lane == 0) {
#pragma unroll
            for (int tt = 0; tt < 2; tt++) {
                int   tok = t0 + tt;
                float rw[NEXP], sc[NEXP];
#pragma unroll
                for (int e = 0; e < NEXP; e++) {
                    float v = tt ? a1[e] : a0[e];
                    rw[e] = 1.f / (1.f + expf(-v));
                    sc[e] = rw[e] + bias[e];
                }
                int i0 = 0; float s0 = sc[0];
#pragma unroll
                for (int e = 1; e < NEXP; e++) if (sc[e] > s0) { s0 = sc[e]; i0 = e; }
                int i1 = -1; float s1 = -1e30f;
#pragma unroll
                for (int e = 0; e < NEXP; e++) {
                    if (e == i0) continue;
                    if (sc[e] > s1) { s1 = sc[e]; i1 = e; }
                }
                float wsum = rw[i0] + rw[i1];
                g_topk_idx[tok * 2 + 0] = i0;
                g_topk_idx[tok * 2 + 1] = i1;
                g_topk_w[tok * 2 + 0] = rw[i0] / wsum;
                g_topk_w[tok * 2 + 1] = rw[i1] / wsum;
                atomicAdd(&g_cnt[i0], 1);
                atomicAdd(&g_cnt[i1], 1);
            }
        }
        return;
    }

    if (b < RBLK + ZBLK) {
        int i = (b - RBLK) * 256 + threadIdx.x;
        if (i < T * (HDIM / 4))
            ((float4*)out)[i] = make_float4(0.f, 0.f, 0.f, 0.f);
        return;
    }

    {
        const size_t nw = (size_t)NEXP * FFN * HDIM / 8;
        size_t i = (size_t)(b - RBLK - ZBLK) * 256 + threadIdx.x;
        const float* s; __half* d; size_t j;
        if (i < nw)          { s = W1; d = g_w1; j = i; }
        else if (i < 2 * nw) { s = W3; d = g_w3; j = i - nw; }
        else if (i < 3 * nw) { s = W2; d = g_w2; j = i - 2 * nw; }
        else return;
        float4 v0 = ((const float4*)s)[j * 2 + 0];
        float4 v1 = ((const float4*)s)[j * 2 + 1];
        union { uint4 u; __half2 h[4]; } o;
        o.h[0] = __halves2half2(__float2half(v0.x), __float2half(v0.y));
        o.h[1] = __halves2half2(__float2half(v0.z), __float2half(v0.w));
        o.h[2] = __halves2half2(__float2half(v1.x), __float2half(v1.y));
        o.h[3] = __halves2half2(__float2half(v1.z), __float2half(v1.w));
        ((uint4*)d)[j] = o.u;
    }
}

// -------------------- offsets + scatter (single block) --------------------
__global__ void offsets_scatter_kernel() {
    if (threadIdx.x == 0) {
        int acc = 0;
        g_off[0] = 0;
        for (int e = 0; e < NEXP; e++) { acc += g_cnt[e]; g_off[e + 1] = acc; }
    }
    __syncthreads();
#pragma unroll
    for (int it = 0; it < T / 1024; it++) {
        int t = it * 1024 + threadIdx.x;
#pragma unroll
        for (int k = 0; k < TOPK; k++) {
            int e = g_topk_idx[t * 2 + k];
            int p = g_off[e] + atomicAdd(&g_cur[e], 1);
            g_perm[p]  = t;
            g_permw[p] = g_topk_w[t * 2 + k];
        }
    }
}

// -------------------- up GEMM: 256M x 64N (W1 & W3), 512 threads ------------
#define UP_A   0
#define UP_B1  (256 * SROW)
#define UP_B3  (UP_B1 + 64 * SROW)
#define UP_STAGE (UP_B3 + 64 * SROW)         // 30720 B
#define UP_SMEM  (3 * UP_STAGE)              // 92160 B

__global__ __launch_bounds__(512, 1) void up_mm() {
    int e    = blockIdx.z;
    int mEnd = g_off[e + 1];
    int m0   = g_off[e] + blockIdx.y * 256;
    if (m0 >= mEnd) return;
    int n0 = blockIdx.x * 64;

    extern __shared__ char smem[];
    uint32_t sb = smem_u32(smem);
    int tid = threadIdx.x, lane = tid & 31, wid = tid >> 5;

    // A loader: thread -> row r (0..255), 2 consecutive 16B segs
    int r = tid >> 1, seg2 = (tid & 1) * 2;
    int  slotL = m0 + r;
    bool va    = slotL < mEnd;
    const __half* ap = g_x + (size_t)(va ? g_perm[slotL] : 0) * HDIM + seg2 * 8;
    uint32_t adst = (uint32_t)(r * SROW + seg2 * 16);
    // B loader: thread -> one 16B seg of B1 (tid<256) or B3
    int brow = tid & 63, bseg = (tid >> 6) & 3;
    int isB3 = tid >> 8;
    const __half* bp = (isB3 ? g_w3 : g_w1) +
                       ((size_t)e * FFN + n0 + brow) * HDIM + bseg * 8;
    uint32_t bdst = (uint32_t)((isB3 ? UP_B3 : UP_B1) + brow * SROW + bseg * 16);

#define UP_LOAD(st, kb) do {                                                    \
        uint32_t o_ = sb + (st) * UP_STAGE;                                     \
        cpa16(o_ + adst,      ap + (kb), va);                                   \
        cpa16(o_ + adst + 16, ap + (kb) + 8, va);                               \
        cpa16(o_ + bdst,      bp + (kb), true);                                 \
        CP_COMMIT();                                                            \
    } while (0)

    int warpM = wid & 7, warpN = wid >> 3;     // 32 rows, 32 cols per warp
    const bool mAct = (m0 + warpM * 32) < mEnd;
    uint32_t aOff = (uint32_t)((lane & 15) * SROW + (lane >> 4) * 16);
    uint32_t bOff = (uint32_t)(((lane & 7) + ((lane >> 4) << 3)) * SROW + ((lane >> 3) & 1) * 16);

    float acc1[2][4][4], acc3[2][4][4];
#pragma unroll
    for (int i = 0; i < 2; i++)
#pragma unroll
        for (int j = 0; j < 4; j++)
#pragma unroll
            for (int q = 0; q < 4; q++) { acc1[i][j][q] = 0.f; acc3[i][j][q] = 0.f; }

    UP_LOAD(0, 0);
    UP_LOAD(1, 32);
    const int NCH = HDIM / 32;
#pragma unroll 1
    for (int c = 0; c < NCH; c++) {
        int buf = c % 3;
        if (c + 2 < NCH) UP_LOAD((c + 2) % 3, (c + 2) * 32);
        else CP_COMMIT();
        CP_WAIT2();
        __syncthreads();

        if (mAct) {
            uint32_t s0 = sb + buf * UP_STAGE;
            uint32_t aA = s0 + UP_A  + (warpM * 32) * SROW + aOff;
            uint32_t b1 = s0 + UP_B1 + (warpN * 32) * SROW + bOff;
            uint32_t b3 = s0 + UP_B3 + (warpN * 32) * SROW + bOff;

#pragma unroll
            for (int ks = 0; ks < 2; ks++) {
                uint32_t ah[2][4];
#pragma unroll
                for (int i = 0; i < 2; i++)
                    LDM4(ah[i], aA + i * 16 * SROW + ks * 32);
#pragma unroll
                for (int jp = 0; jp < 2; jp++) {
                    uint32_t bb[4];
                    LDM4(bb, b1 + jp * 16 * SROW + ks * 32);
#pragma unroll
                    for (int i = 0; i < 2; i++) {
                        MMAH(acc1[i][2 * jp],     ah[i], bb[0], bb[1]);
                        MMAH(acc1[i][2 * jp + 1], ah[i], bb[2], bb[3]);
                    }
                }
#pragma unroll
                for (int jp = 0; jp < 2; jp++) {
                    uint32_t bb[4];
                    LDM4(bb, b3 + jp * 16 * SROW + ks * 32);
#pragma unroll
                    for (int i = 0; i < 2; i++) {
                        MMAH(acc3[i][2 * jp],     ah[i], bb[0], bb[1]);
                        MMAH(acc3[i][2 * jp + 1], ah[i], bb[2], bb[3]);
                    }
                }
            }
        }
        __syncthreads();
    }

    // epilogue: SwiGLU * weight -> G (fp16)
#pragma unroll
    for (int i = 0; i < 2; i++) {
#pragma unroll
        for (int h = 0; h < 2; h++) {
            int rloc = warpM * 32 + i * 16 + (lane >> 2) + h * 8;
            int slot = m0 + rloc;
            if (slot < mEnd) {
                float w = g_permw[slot];
                size_t rowoff = (size_t)slot * FFN;
#pragma unroll
                for (int j = 0; j < 4; j++) {
                    float d1a = acc1[i][j][2 * h], d1b = acc1[i][j][2 * h + 1];
                    float d3a = acc3[i][j][2 * h], d3b = acc3[i][j][2 * h + 1];
                    float ga = d1a / (1.f + expf(-d1a)) * d3a * w;
                    float gb = d1b / (1.f + expf(-d1b)) * d3b * w;
                    int cc = n0 + warpN * 32 + j * 8 + (lane & 3) * 2;
                    *(__half2*)(g_G + rowoff + cc) =
                        __halves2half2(__float2half(ga), __float2half(gb));
                }
            }
        }
    }
#undef UP_LOAD
}

// -------------------- down GEMM: 256M x 128N, 512 threads, atomic combine ---
#define DN_A   0
#define DN_B   (256 * SROW)
#define DN_STAGE (DN_B + 128 * SROW)         // 30720 B
#define DN_SMEM  (3 * DN_STAGE)

__global__ __launch_bounds__(512, 1) void down_mm(float* __restrict__ out) {
    int e    = blockIdx.z;
    int mEnd = g_off[e + 1];
    int m0   = g_off[e] + blockIdx.y * 256;
    if (m0 >= mEnd) return;
    int n0 = blockIdx.x * 128;

    extern __shared__ char smem[];
    uint32_t sb = smem_u32(smem);
    int tid = threadIdx.x, lane = tid & 31, wid = tid >> 5;

    // A loader: thread -> row r (0..255), 2 consecutive 16B segs
    int r = tid >> 1, seg2 = (tid & 1) * 2;
    int  slotL = m0 + r;
    bool va    = slotL < mEnd;
    const __half* ap = g_G + (size_t)(va ? slotL : 0) * FFN + seg2 * 8;
    uint32_t adst = (uint32_t)(r * SROW + seg2 * 16);
    // B loader: thread -> one 16B seg (128 rows x 4 segs)
    int brow = tid & 127, bseg = (tid >> 7) & 3;
    const __half* bp = g_w2 + ((size_t)e * HDIM + n0 + brow) * FFN + bseg * 8;
    uint32_t bdst = (uint32_t)(DN_B + brow * SROW + bseg * 16);

#define DN_LOAD(st, kb) do {                                                    \
        uint32_t o_ = sb + (st) * DN_STAGE;                                     \
        cpa16(o_ + adst,      ap + (kb), va);                                   \
        cpa16(o_ + adst + 16, ap + (kb) + 8, va);                               \
        cpa16(o_ + bdst,      bp + (kb), true);                                 \
        CP_COMMIT();                                                            \
    } while (0)

    int warpM = wid & 7, warpN = wid >> 3;     // 32 rows, 64 cols per warp
    const bool mAct = (m0 + warpM * 32) < mEnd;
    uint32_t aOff = (uint32_t)((lane & 15) * SROW + (lane >> 4) * 16);
    uint32_t bOff = (uint32_t)(((lane & 7) + ((lane >> 4) << 3)) * SROW + ((lane >> 3) & 1) * 16);

    float acc[2][8][4];
#pragma unroll
    for (int i = 0; i < 2; i++)
#pragma unroll
        for (int j = 0; j < 8; j++)
#pragma unroll
            for (int q = 0; q < 4; q++) acc[i][j][q] = 0.f;

    DN_LOAD(0, 0);
    DN_LOAD(1, 32);
    const int NCH = FFN / 32;
#pragma unroll 1
    for (int c = 0; c < NCH; c++) {
        int buf = c % 3;
        if (c + 2 < NCH) DN_LOAD((c + 2) % 3, (c + 2) * 32);
        else CP_COMMIT();
        CP_WAIT2();
        __syncthreads();

        if (mAct) {
            uint32_t s0 = sb + buf * DN_STAGE;
            uint32_t aA = s0 + DN_A + (warpM * 32) * SROW + aOff;
            uint32_t bB = s0 + DN_B + (warpN * 64) * SROW + bOff;

#pragma unroll
            for (int ks = 0; ks < 2; ks++) {
                uint32_t ah[2][4];
#pragma unroll
                for (int i = 0; i < 2; i++)
                    LDM4(ah[i], aA + i * 16 * SROW + ks * 32);
#pragma unroll
                for (int jp = 0; jp < 4; jp++) {
                    uint32_t bb[4];
                    LDM4(bb, bB + jp * 16 * SROW + ks * 32);
#pragma unroll
                    for (int i = 0; i < 2; i++) {
                        MMAH(acc[i][2 * jp],     ah[i], bb[0], bb[1]);
                        MMAH(acc[i][2 * jp + 1], ah[i], bb[2], bb[3]);
                    }
                }
            }
        }
        __syncthreads();
    }

    // epilogue: atomic combine into out (exactly 2 contributions/element ->
    // fp32 add is commutative -> deterministic)
#pragma unroll
    for (int i = 0; i < 2; i++) {
#pragma unroll
        for (int h = 0; h < 2; h++) {
            int rloc = warpM * 32 + i * 16 + (lane >> 2) + h * 8;
            int slot = m0 + rloc;
            if (slot < mEnd) {
                int tokE = g_perm[slot];
                float* yrow = out + (size_t)tokE * HDIM;
#pragma unroll
                for (int j = 0; j < 8; j++) {
                    int cc = n0 + warpN * 64 + j * 8 + (lane & 3) * 2;
                    atomicAdd(&yrow[cc],     acc[i][j][2 * h]);
                    atomicAdd(&yrow[cc + 1], acc[i][j][2 * h + 1]);
                }
            }
        }
    }
#undef DN_LOAD
}

// -------------------- launcher --------------------
extern "C" void kernel_launch(void* const* d_in, const int* in_sizes, int n_in,
                              void* d_out, int out_size) {
    const float* x    = (const float*)d_in[0];
    const float* Wg   = (const float*)d_in[1];
    const float* W1   = (const float*)d_in[2];
    const float* W2   = (const float*)d_in[3];
    const float* W3   = (const float*)d_in[4];
    const float* bias = (const float*)d_in[5];
    float* out = (float*)d_out;

    cudaFuncSetAttribute(up_mm,   cudaFuncAttributeMaxDynamicSharedMemorySize, UP_SMEM);
    cudaFuncSetAttribute(down_mm, cudaFuncAttributeMaxDynamicSharedMemorySize, DN_SMEM);

    prep_kernel<<<PREP_BLOCKS, 256>>>(x, Wg, bias, W1, W3, W2, out);  // 0
    offsets_scatter_kernel<<<1, 1024>>>();                            // 1

    dim3 upGrid(FFN / 64, T / 256, NEXP);
    up_mm<<<upGrid, 512, UP_SMEM>>>();                                // 2

    dim3 dnGrid(HDIM / 128, T / 256, NEXP);
    down_mm<<<dnGrid, 512, DN_SMEM>>>(out);                           // 3
}

// round 15
// speedup vs baseline: 1.2765x; 1.2765x over previous
#include <cuda_runtime.h>
#include <cuda_fp16.h>
#include <math.h>
#include <stdint.h>

// -------------------- problem constants --------------------
#define T      4096
#define HDIM   2048
#define FFN    1024
#define NEXP   8
#define TOPK   2
#define SLOTS  (T * TOPK)

// -------------------- scratch (device globals; no allocs) --------------------
__device__ int   g_topk_idx[T * TOPK];
__device__ float g_topk_w[T * TOPK];
__device__ int   g_cnt[NEXP];
__device__ int   g_cur[NEXP];
__device__ int   g_off[NEXP + 1];
__device__ int   g_perm[SLOTS];
__device__ float g_permw[SLOTS];

__device__ __half g_x [(size_t)T * HDIM];
__device__ __half g_w1[(size_t)NEXP * FFN * HDIM];
__device__ __half g_w3[(size_t)NEXP * FFN * HDIM];
__device__ __half g_w2[(size_t)NEXP * HDIM * FFN];
__device__ __half g_G [(size_t)SLOTS * FFN];

// -------------------- helpers --------------------
__device__ __forceinline__ uint32_t smem_u32(const void* p) {
    uint32_t a;
    asm("{ .reg .u64 t; cvta.to.shared.u64 t, %1; cvt.u32.u64 %0, t; }" : "=r"(a) : "l"(p));
    return a;
}
__device__ __forceinline__ void cpa16(uint32_t dst, const void* src, bool v) {
    uint64_t g = __cvta_generic_to_global(src);
    int sz = v ? 16 : 0;
    asm volatile("cp.async.cg.shared.global [%0], [%1], 16, %2;"
                 :: "r"(dst), "l"(g), "r"(sz) : "memory");
}
#define CP_COMMIT() asm volatile("cp.async.commit_group;" ::: "memory")
#define CP_WAIT4()  asm volatile("cp.async.wait_group 4;" ::: "memory")

#define LDM4(r, a) \
    asm volatile("ldmatrix.sync.aligned.m8n8.x4.shared.b16 {%0,%1,%2,%3}, [%4];" \
        : "=r"((r)[0]), "=r"((r)[1]), "=r"((r)[2]), "=r"((r)[3]) : "r"(a))

#define MMAH(d, a, b0, b1) \
    asm volatile("mma.sync.aligned.m16n8k16.row.col.f32.f16.f16.f32 " \
        "{%0,%1,%2,%3},{%4,%5,%6,%7},{%8,%9},{%0,%1,%2,%3};" \
        : "+f"((d)[0]), "+f"((d)[1]), "+f"((d)[2]), "+f"((d)[3]) \
        : "r"((a)[0]), "r"((a)[1]), "r"((a)[2]), "r"((a)[3]), "r"(b0), "r"(b1))

// smem row stride: 32 fp16 (64B) + 16B pad = 80 B (conflict-free ldmatrix)
#define SROW 80

// -------------------- fused prep: router + zero_out + convert ---------------
#define RBLK (T / 16)                                    // 256 (2 tokens/warp)
#define ZBLK (T * (HDIM / 4) / 256)                      // 8192
#define CBLK ((3u * (NEXP * FFN * HDIM / 8) + 255) / 256)   // 24576
#define PREP_BLOCKS (RBLK + ZBLK + CBLK)

__global__ void prep_kernel(const float* __restrict__ x,
                            const float* __restrict__ Wg,
                            const float* __restrict__ bias,
                            const float* __restrict__ W1,
                            const float* __restrict__ W3,
                            const float* __restrict__ W2,
                            float* __restrict__ out) {
    int b = blockIdx.x;

    if (b < RBLK) {
        int warp = (b * 256 + threadIdx.x) >> 5;
        int lane = threadIdx.x & 31;
        if (b == 0 && threadIdx.x < NEXP) {
            g_cnt[threadIdx.x] = 0;
            g_cur[threadIdx.x] = 0;
        }
        int t0 = warp * 2, t1 = t0 + 1;
        const float* xr0 = x + (size_t)t0 * HDIM;
        const float* xr1 = x + (size_t)t1 * HDIM;
        __half* xo0 = g_x + (size_t)t0 * HDIM;
        __half* xo1 = g_x + (size_t)t1 * HDIM;

        float a0[NEXP], a1[NEXP];
#pragma unroll
        for (int e = 0; e < NEXP; e++) { a0[e] = 0.f; a1[e] = 0.f; }

        for (int k = lane * 4; k < HDIM; k += 32 * 4) {
            float4 xv0 = *(const float4*)(xr0 + k);
            float4 xv1 = *(const float4*)(xr1 + k);
            union { uint2 u; __half2 h[2]; } c0, c1;
            c0.h[0] = __halves2half2(__float2half(xv0.x), __float2half(xv0.y));
            c0.h[1] = __halves2half2(__float2half(xv0.z), __float2half(xv0.w));
            c1.h[0] = __halves2half2(__float2half(xv1.x), __float2half(xv1.y));
            c1.h[1] = __halves2half2(__float2half(xv1.z), __float2half(xv1.w));
            *(uint2*)(xo0 + k) = c0.u;
            *(uint2*)(xo1 + k) = c1.u;
#pragma unroll
            for (int e = 0; e < NEXP; e++) {
                float4 wv = *(const float4*)(Wg + (size_t)e * HDIM + k);
                a0[e] += xv0.x * wv.x + xv0.y * wv.y + xv0.z * wv.z + xv0.w * wv.w;
                a1[e] += xv1.x * wv.x + xv1.y * wv.y + xv1.z * wv.z + xv1.w * wv.w;
            }
        }
#pragma unroll
        for (int e = 0; e < NEXP; e++) {
#pragma unroll
            for (int o = 16; o > 0; o >>= 1) {
                a0[e] += __shfl_xor_sync(0xFFFFFFFFu, a0[e], o);
                a1[e] += __shfl_xor_sync(0xFFFFFFFFu, a1[e], o);
            }
        }
        if (lane == 0) {
#pragma unroll
            for (int tt = 0; tt < 2; tt++) {
                int   tok = t0 + tt;
                float rw[NEXP], sc[NEXP];
#pragma unroll
                for (int e = 0; e < NEXP; e++) {
                    float v = tt ? a1[e] : a0[e];
                    rw[e] = 1.f / (1.f + expf(-v));
                    sc[e] = rw[e] + bias[e];
                }
                int i0 = 0; float s0 = sc[0];
#pragma unroll
                for (int e = 1; e < NEXP; e++) if (sc[e] > s0) { s0 = sc[e]; i0 = e; }
                int i1 = -1; float s1 = -1e30f;
#pragma unroll
                for (int e = 0; e < NEXP; e++) {
                    if (e == i0) continue;
                    if (sc[e] > s1) { s1 = sc[e]; i1 = e; }
                }
                float wsum = rw[i0] + rw[i1];
                g_topk_idx[tok * 2 + 0] = i0;
                g_topk_idx[tok * 2 + 1] = i1;
                g_topk_w[tok * 2 + 0] = rw[i0] / wsum;
                g_topk_w[tok * 2 + 1] = rw[i1] / wsum;
                atomicAdd(&g_cnt[i0], 1);
                atomicAdd(&g_cnt[i1], 1);
            }
        }
        return;
    }

    if (b < RBLK + ZBLK) {
        int i = (b - RBLK) * 256 + threadIdx.x;
        if (i < T * (HDIM / 4))
            ((float4*)out)[i] = make_float4(0.f, 0.f, 0.f, 0.f);
        return;
    }

    {
        const size_t nw = (size_t)NEXP * FFN * HDIM / 8;
        size_t i = (size_t)(b - RBLK - ZBLK) * 256 + threadIdx.x;
        const float* s; __half* d; size_t j;
        if (i < nw)          { s = W1; d = g_w1; j = i; }
        else if (i < 2 * nw) { s = W3; d = g_w3; j = i - nw; }
        else if (i < 3 * nw) { s = W2; d = g_w2; j = i - 2 * nw; }
        else return;
        float4 v0 = ((const float4*)s)[j * 2 + 0];
        float4 v1 = ((const float4*)s)[j * 2 + 1];
        union { uint4 u; __half2 h[4]; } o;
        o.h[0] = __halves2half2(__float2half(v0.x), __float2half(v0.y));
        o.h[1] = __halves2half2(__float2half(v0.z), __float2half(v0.w));
        o.h[2] = __halves2half2(__float2half(v1.x), __float2half(v1.y));
        o.h[3] = __halves2half2(__float2half(v1.z), __float2half(v1.w));
        ((uint4*)d)[j] = o.u;
    }
}

// -------------------- offsets + scatter (single block) --------------------
__global__ void offsets_scatter_kernel() {
    if (threadIdx.x == 0) {
        int acc = 0;
        g_off[0] = 0;
        for (int e = 0; e < NEXP; e++) { acc += g_cnt[e]; g_off[e + 1] = acc; }
    }
    __syncthreads();
#pragma unroll
    for (int it = 0; it < T / 1024; it++) {
        int t = it * 1024 + threadIdx.x;
#pragma unroll
        for (int k = 0; k < TOPK; k++) {
            int e = g_topk_idx[t * 2 + k];
            int p = g_off[e] + atomicAdd(&g_cur[e], 1);
            g_perm[p]  = t;
            g_permw[p] = g_topk_w[t * 2 + k];
        }
    }
}

// -------------------- up GEMM: 256M x 64N (W1 & W3), 6-stage paired ---------
#define UP_A   0
#define UP_B1  (256 * SROW)
#define UP_B3  (UP_B1 + 64 * SROW)
#define UP_STAGE (UP_B3 + 64 * SROW)         // 30720 B
#define UP_SMEM  (6 * UP_STAGE)              // 184320 B

__global__ __launch_bounds__(256, 1) void up_mm() {
    int e    = blockIdx.z;
    int mEnd = g_off[e + 1];
    int m0   = g_off[e] + blockIdx.y * 256;
    if (m0 >= mEnd) return;
    int n0 = blockIdx.x * 64;

    extern __shared__ char smem[];
    uint32_t sb = smem_u32(smem);
    int tid = threadIdx.x, lane = tid & 31, wid = tid >> 5;

    int r = tid >> 2, seg = tid & 3;
    bool  va[4]; int tok[4];
#pragma unroll
    for (int q = 0; q < 4; q++) {
        int slot = m0 + r + 64 * q;
        va[q]  = slot < mEnd;
        tok[q] = va[q] ? g_perm[slot] : 0;
    }
    size_t browo = ((size_t)e * FFN + n0 + r) * HDIM + seg * 8;
    const __half* b1p = g_w1 + browo;
    const __half* b3p = g_w3 + browo;

#define UP_LOAD(st, kb) do {                                                    \
        uint32_t o_ = sb + (st) * UP_STAGE;                                     \
        _Pragma("unroll")                                                       \
        for (int q = 0; q < 4; q++) {                                           \
            uint32_t d_ = o_ + UP_A + (r + 64 * q) * SROW + seg * 16;           \
            const __half* sa = g_x + (size_t)tok[q] * HDIM + seg * 8 + (kb);    \
            cpa16(d_, sa, va[q]);                                               \
        }                                                                       \
        uint32_t db_ = o_ + r * SROW + seg * 16;                                \
        cpa16(db_ + UP_B1, b1p + (kb), true);                                   \
        cpa16(db_ + UP_B3, b3p + (kb), true);                                   \
        CP_COMMIT();                                                            \
    } while (0)

    int warpM = wid & 3, warpN = wid >> 2;
    const bool mAct = (m0 + warpM * 64) < mEnd;
    uint32_t aOff = (uint32_t)((lane & 15) * SROW + (lane >> 4) * 16);
    uint32_t bOff = (uint32_t)(((lane & 7) + ((lane >> 4) << 3)) * SROW + ((lane >> 3) & 1) * 16);

    float acc1[4][4][4], acc3[4][4][4];
#pragma unroll
    for (int i = 0; i < 4; i++)
#pragma unroll
        for (int j = 0; j < 4; j++)
#pragma unroll
            for (int q = 0; q < 4; q++) { acc1[i][j][q] = 0.f; acc3[i][j][q] = 0.f; }

    UP_LOAD(0, 0);
    UP_LOAD(1, 32);
    UP_LOAD(2, 64);
    UP_LOAD(3, 96);
    const int NCH = HDIM / 32;
#pragma unroll 1
    for (int c = 0; c < NCH; c += 2) {
        if (c + 4 < NCH) UP_LOAD((c + 4) % 6, (c + 4) * 32); else CP_COMMIT();
        if (c + 5 < NCH) UP_LOAD((c + 5) % 6, (c + 5) * 32); else CP_COMMIT();
        CP_WAIT4();
        __syncthreads();

        if (mAct) {
#pragma unroll
            for (int cc = 0; cc < 2; cc++) {
                uint32_t s0 = sb + ((c + cc) % 6) * UP_STAGE;
                uint32_t aA = s0 + UP_A  + (warpM * 64) * SROW + aOff;
                uint32_t b1 = s0 + UP_B1 + (warpN * 32) * SROW + bOff;
                uint32_t b3 = s0 + UP_B3 + (warpN * 32) * SROW + bOff;

#pragma unroll
                for (int ks = 0; ks < 2; ks++) {
                    uint32_t ah[4][4];
#pragma unroll
                    for (int i = 0; i < 4; i++)
                        LDM4(ah[i], aA + i * 16 * SROW + ks * 32);
#pragma unroll
                    for (int jp = 0; jp < 2; jp++) {
                        uint32_t bb[4];
                        LDM4(bb, b1 + jp * 16 * SROW + ks * 32);
#pragma unroll
                        for (int i = 0; i < 4; i++) {
                            MMAH(acc1[i][2 * jp],     ah[i], bb[0], bb[1]);
                            MMAH(acc1[i][2 * jp + 1], ah[i], bb[2], bb[3]);
                        }
                    }
#pragma unroll
                    for (int jp = 0; jp < 2; jp++) {
                        uint32_t bb[4];
                        LDM4(bb, b3 + jp * 16 * SROW + ks * 32);
#pragma unroll
                        for (int i = 0; i < 4; i++) {
                            MMAH(acc3[i][2 * jp],     ah[i], bb[0], bb[1]);
                            MMAH(acc3[i][2 * jp + 1], ah[i], bb[2], bb[3]);
                        }
                    }
                }
            }
        }
        __syncthreads();
    }

    // epilogue: SwiGLU * weight -> G (fp16)
#pragma unroll
    for (int i = 0; i < 4; i++) {
#pragma unroll
        for (int h = 0; h < 2; h++) {
            int rloc = warpM * 64 + i * 16 + (lane >> 2) + h * 8;
            int slot = m0 + rloc;
            if (slot < mEnd) {
                float w = g_permw[slot];
                size_t rowoff = (size_t)slot * FFN;
#pragma unroll
                for (int j = 0; j < 4; j++) {
                    float d1a = acc1[i][j][2 * h], d1b = acc1[i][j][2 * h + 1];
                    float d3a = acc3[i][j][2 * h], d3b = acc3[i][j][2 * h + 1];
                    float ga = d1a / (1.f + expf(-d1a)) * d3a * w;
                    float gb = d1b / (1.f + expf(-d1b)) * d3b * w;
                    int cc = n0 + warpN * 32 + j * 8 + (lane & 3) * 2;
                    *(__half2*)(g_G + rowoff + cc) =
                        __halves2half2(__float2half(ga), __float2half(gb));
                }
            }
        }
    }
#undef UP_LOAD
}

// -------------------- down GEMM: 256M x 128N, 6-stage paired, atomic --------
#define DN_A   0
#define DN_B   (256 * SROW)
#define DN_STAGE (DN_B + 128 * SROW)         // 30720 B
#define DN_SMEM  (6 * DN_STAGE)              // 184320 B

__global__ __launch_bounds__(256, 1) void down_mm(float* __restrict__ out) {
    int e    = blockIdx.z;
    int mEnd = g_off[e + 1];
    int m0   = g_off[e] + blockIdx.y * 256;
    if (m0 >= mEnd) return;
    int n0 = blockIdx.x * 128;

    extern __shared__ char smem[];
    uint32_t sb = smem_u32(smem);
    int tid = threadIdx.x, lane = tid & 31, wid = tid >> 5;

    int r = tid >> 2, seg = tid & 3;
    bool va[4]; int srow[4];
#pragma unroll
    for (int q = 0; q < 4; q++) {
        int slot = m0 + r + 64 * q;
        va[q]   = slot < mEnd;
        srow[q] = va[q] ? slot : 0;
    }
    size_t brow0 = ((size_t)e * HDIM + n0 + r) * FFN + seg * 8;
    size_t brow1 = ((size_t)e * HDIM + n0 + r + 64) * FFN + seg * 8;
    const __half* bp0 = g_w2 + brow0;
    const __half* bp1 = g_w2 + brow1;

#define DN_LOAD(st, kb) do {                                                    \
        uint32_t o_ = sb + (st) * DN_STAGE;                                     \
        _Pragma("unroll")                                                       \
        for (int q = 0; q < 4; q++) {                                           \
            uint32_t d_ = o_ + DN_A + (r + 64 * q) * SROW + seg * 16;           \
            const __half* sa = g_G + (size_t)srow[q] * FFN + seg * 8 + (kb);    \
            cpa16(d_, sa, va[q]);                                               \
        }                                                                       \
        uint32_t db0 = o_ + r * SROW + seg * 16;                                \
        uint32_t db1 = o_ + (r + 64) * SROW + seg * 16;                         \
        cpa16(db0 + DN_B, bp0 + (kb), true);                                    \
        cpa16(db1 + DN_B, bp1 + (kb), true);                                    \
        CP_COMMIT();                                                            \
    } while (0)

    int warpM = wid & 3, warpN = wid >> 2;
    const bool mAct = (m0 + warpM * 64) < mEnd;
    uint32_t aOff = (uint32_t)((lane & 15) * SROW + (lane >> 4) * 16);
    uint32_t bOff = (uint32_t)(((lane & 7) + ((lane >> 4) << 3)) * SROW + ((lane >> 3) & 1) * 16);

    float acc[4][8][4];
#pragma unroll
    for (int i = 0; i < 4; i++)
#pragma unroll
        for (int j = 0; j < 8; j++)
#pragma unroll
            for (int q = 0; q < 4; q++) acc[i][j][q] = 0.f;

    DN_LOAD(0, 0);
    DN_LOAD(1, 32);
    DN_LOAD(2, 64);
    DN_LOAD(3, 96);
    const int NCH = FFN / 32;
#pragma unroll 1
    for (int c = 0; c < NCH; c += 2) {
        if (c + 4 < NCH) DN_LOAD((c + 4) % 6, (c + 4) * 32); else CP_COMMIT();
        if (c + 5 < NCH) DN_LOAD((c + 5) % 6, (c + 5) * 32); else CP_COMMIT();
        CP_WAIT4();
        __syncthreads();

        if (mAct) {
#pragma unroll
            for (int cc = 0; cc < 2; cc++) {
                uint32_t s0 = sb + ((c + cc) % 6) * DN_STAGE;
                uint32_t aA = s0 + DN_A + (warpM * 64) * SROW + aOff;
                uint32_t bB = s0 + DN_B + (warpN * 64) * SROW + bOff;

#pragma unroll
                for (int ks = 0; ks < 2; ks++) {
                    uint32_t ah[4][4];
#pragma unroll
                    for (int i = 0; i < 4; i++)
                        LDM4(ah[i], aA + i * 16 * SROW + ks * 32);
#pragma unroll
                    for (int jp = 0; jp < 4; jp++) {
                        uint32_t bb[4];
                        LDM4(bb, bB + jp * 16 * SROW + ks * 32);
#pragma unroll
                        for (int i = 0; i < 4; i++) {
                            MMAH(acc[i][2 * jp],     ah[i], bb[0], bb[1]);
                            MMAH(acc[i][2 * jp + 1], ah[i], bb[2], bb[3]);
                        }
                    }
                }
            }
        }
        __syncthreads();
    }

    // epilogue: atomic combine into out (exactly 2 contributions/element ->
    // fp32 add is commutative -> deterministic)
#pragma unroll
    for (int i = 0; i < 4; i++) {
#pragma unroll
        for (int h = 0; h < 2; h++) {
            int rloc = warpM * 64 + i * 16 + (lane >> 2) + h * 8;
            int slot = m0 + rloc;
            if (slot < mEnd) {
                int tokE = g_perm[slot];
                float* yrow = out + (size_t)tokE * HDIM;
#pragma unroll
                for (int j = 0; j < 8; j++) {
                    int cc = n0 + warpN * 64 + j * 8 + (lane & 3) * 2;
                    atomicAdd(&yrow[cc],     acc[i][j][2 * h]);
                    atomicAdd(&yrow[cc + 1], acc[i][j][2 * h + 1]);
                }
            }
        }
    }
#undef DN_LOAD
}

// -------------------- launcher --------------------
extern "C" void kernel_launch(void* const* d_in, const int* in_sizes, int n_in,
                              void* d_out, int out_size) {
    const float* x    = (const float*)d_in[0];
    const float* Wg   = (const float*)d_in[1];
    const float* W1   = (const float*)d_in[2];
    const float* W2   = (const float*)d_in[3];
    const float* W3   = (const float*)d_in[4];
    const float* bias = (const float*)d_in[5];
    float* out = (float*)d_out;

    cudaFuncSetAttribute(up_mm,   cudaFuncAttributeMaxDynamicSharedMemorySize, UP_SMEM);
    cudaFuncSetAttribute(down_mm, cudaFuncAttributeMaxDynamicSharedMemorySize, DN_SMEM);

    prep_kernel<<<PREP_BLOCKS, 256>>>(x, Wg, bias, W1, W3, W2, out);  // 0
    offsets_scatter_kernel<<<1, 1024>>>();                            // 1

    dim3 upGrid(FFN / 64, T / 256, NEXP);
    up_mm<<<upGrid, 256, UP_SMEM>>>();                                // 2

    dim3 dnGrid(HDIM / 128, T / 256, NEXP);
    down_mm<<<dnGrid, 256, DN_SMEM>>>(out);                           // 3
}